// round 13
// baseline (speedup 1.0000x reference)
#include <cuda_runtime.h>
#include <math.h>

#define NS 512
#define DD 400
#define HH 400
#define HP 416   // padded hidden dim (13 * 32); pad rows stay statically zero

typedef unsigned long long u64;

// ---- scratch (no allocations; __device__ globals are zero-initialized) ----
__device__ float  g_hxT[HP * NS];   // [h][sample]; rows 400..415 never written (zero)
__device__ u64    g_hyTd[HP * NS];  // dup'd (y,y) per element (b1 folded); pad zero
__device__ u64    g_w2h[HP];        // dup'd (W2/2, W2/2); pad zero
__device__ float  g_rx[NS];         // sum_h hx[j,h]*W2[h]      (re-zeroed by finalize)
__device__ float  g_ry[NS];         // sum_h (hy[i,h]+b1)*W2[h] (re-zeroed by finalize)
__device__ float  g_expsum[NS];     // per-row sum of exp(T1) = 1 + e^v
__device__ double g_tsum;           // sum of all T1
__device__ double g_dsum;           // sum of diag T1 (== T0 sum)
__device__ int    g_cnt = 0;

// ---- packed f32x2 helpers (sm_10x) ----
#define PACK2(d, lo, hi) \
    asm("mov.b64 %0, {%1,%2};" : "=l"(d) : "f"(lo), "f"(hi))
#define FMA2(acc, a, b) \
    asm("fma.rn.f32x2 %0, %1, %2, %0;" : "+l"(acc) : "l"(a), "l"(b))
// acc2 += |y2 + x2| * w2   (componentwise; abs via sign-mask AND)
#define ABS_FMA2(acc, y2, x2, w2)                       \
    asm("{\n\t"                                         \
        ".reg .b64 t;\n\t"                              \
        "add.rn.f32x2 t, %1, %2;\n\t"                   \
        "and.b64 t, t, 0x7FFFFFFF7FFFFFFF;\n\t"         \
        "fma.rn.f32x2 %0, t, %3, %0;\n\t"               \
        "}" : "+l"(acc) : "l"(y2), "l"(x2), "l"(w2))

// ======================================================================
// Kernel 1: dual GEMM (unchanged from R12 for attribution).
// ======================================================================
__global__ void __launch_bounds__(128)
gemm_h_kernel(const float* __restrict__ x,
              const float* __restrict__ y,
              const float* __restrict__ W1,
              const float* __restrict__ b1,
              const float* __restrict__ W2) {
    const int z = blockIdx.z;

    if (z == 0 && blockIdx.x == 0 && blockIdx.y == 0) {
        #pragma unroll
        for (int r = 0; r < 4; r++) g_expsum[threadIdx.x + r * 128] = 0.f;
        for (int r = threadIdx.x; r < HP; r += 128) {
            float w = (r < HH) ? W2[r] * 0.5f : 0.f;
            u64 wd; PACK2(wd, w, w);
            g_w2h[r] = wd;
        }
        if (threadIdx.x == 0) { g_tsum = 0.0; g_dsum = 0.0; g_cnt = 0; }
    }

    const float* A   = z ? y : x;
    const int   woff = z ? DD : 0;
    float*      rdot = z ? g_ry  : g_rx;

    const int m0 = blockIdx.x * 64;
    const int h0 = blockIdx.y * 32;

    __shared__ __align__(16) float As[16][64];  // [k][m]
    __shared__ __align__(16) u64   Hd[16][32];  // [k][h] dup'd (w,w)
    __shared__ float rsum[64];

    const int tid = threadIdx.x;       // 128
    const int tx  = tid & 15;          // m quad: 4 m each
    const int ty  = tid >> 4;          // h quad: 4 h each (0..7)

    const int s_row = tid >> 2;        // 0..31
    const int s_q   = (tid & 3) * 4;   // k quad
    const bool h_ok = (h0 + s_row) < HH;

    float4 a0, a1, hw;

    a0 = *reinterpret_cast<const float4*>(&A[(m0 + s_row) * DD + s_q]);
    a1 = *reinterpret_cast<const float4*>(&A[(m0 + s_row + 32) * DD + s_q]);
    hw = make_float4(0.f, 0.f, 0.f, 0.f);
    if (h_ok)
        hw = *reinterpret_cast<const float4*>(&W1[(h0 + s_row) * (2 * DD) + woff + s_q]);

    u64 acc[4][2] = {};   // [ih][m-pair]

    const int NT = DD / 16;   // 25
    for (int t = 0; t < NT; t++) {
        As[s_q + 0][s_row] = a0.x; As[s_q + 1][s_row] = a0.y;
        As[s_q + 2][s_row] = a0.z; As[s_q + 3][s_row] = a0.w;
        As[s_q + 0][s_row + 32] = a1.x; As[s_q + 1][s_row + 32] = a1.y;
        As[s_q + 2][s_row + 32] = a1.z; As[s_q + 3][s_row + 32] = a1.w;
        u64 d0, d1, d2, d3;
        PACK2(d0, hw.x, hw.x); PACK2(d1, hw.y, hw.y);
        PACK2(d2, hw.z, hw.z); PACK2(d3, hw.w, hw.w);
        Hd[s_q + 0][s_row] = d0; Hd[s_q + 1][s_row] = d1;
        Hd[s_q + 2][s_row] = d2; Hd[s_q + 3][s_row] = d3;
        __syncthreads();

        if (t + 1 < NT) {
            int k0 = (t + 1) * 16;
            a0 = *reinterpret_cast<const float4*>(&A[(m0 + s_row) * DD + k0 + s_q]);
            a1 = *reinterpret_cast<const float4*>(&A[(m0 + s_row + 32) * DD + k0 + s_q]);
            if (h_ok)
                hw = *reinterpret_cast<const float4*>(&W1[(h0 + s_row) * (2 * DD) + woff + k0 + s_q]);
        }

        #pragma unroll
        for (int kk = 0; kk < 16; kk++) {
            ulonglong2 h01 = *reinterpret_cast<const ulonglong2*>(&Hd[kk][ty * 4 + 0]);
            ulonglong2 h23 = *reinterpret_cast<const ulonglong2*>(&Hd[kk][ty * 4 + 2]);
            ulonglong2 mm  = *reinterpret_cast<const ulonglong2*>(&As[kk][tx * 4]);
            FMA2(acc[0][0], h01.x, mm.x); FMA2(acc[0][1], h01.x, mm.y);
            FMA2(acc[1][0], h01.y, mm.x); FMA2(acc[1][1], h01.y, mm.y);
            FMA2(acc[2][0], h23.x, mm.x); FMA2(acc[2][1], h23.x, mm.y);
            FMA2(acc[3][0], h23.y, mm.x); FMA2(acc[3][1], h23.y, mm.y);
        }
        __syncthreads();
    }

    if (tid < 64) rsum[tid] = 0.f;
    __syncthreads();

    float part[4] = {0.f, 0.f, 0.f, 0.f};
    #pragma unroll
    for (int ih = 0; ih < 4; ih++) {
        const int h = h0 + ty * 4 + ih;
        const bool valid = h < HH;
        const float b  = (z && valid) ? b1[h] : 0.f;
        const float wv = valid ? W2[h] : 0.f;
        float2 p0 = *reinterpret_cast<float2*>(&acc[ih][0]);
        float2 p1 = *reinterpret_cast<float2*>(&acc[ih][1]);
        float v0 = p0.x + b, v1 = p0.y + b, v2 = p1.x + b, v3 = p1.y + b;
        if (valid) {
            if (z) {
                u64 q0, q1, q2, q3;
                PACK2(q0, v0, v0); PACK2(q1, v1, v1);
                PACK2(q2, v2, v2); PACK2(q3, v3, v3);
                ulonglong2* o = reinterpret_cast<ulonglong2*>(&g_hyTd[h * NS + m0 + tx * 4]);
                o[0] = make_ulonglong2(q0, q1);
                o[1] = make_ulonglong2(q2, q3);
            } else {
                *reinterpret_cast<float4*>(&g_hxT[h * NS + m0 + tx * 4]) =
                    make_float4(v0, v1, v2, v3);
            }
        }
        part[0] += v0 * wv; part[1] += v1 * wv;
        part[2] += v2 * wv; part[3] += v3 * wv;
    }
    #pragma unroll
    for (int mm = 0; mm < 4; mm++)
        atomicAdd(&rsum[tx * 4 + mm], part[mm]);
    __syncthreads();
    if (tid < 64) atomicAdd(&rdot[m0 + tid], rsum[tid]);
}

// ======================================================================
// Kernel 2: pair abs-dot — WHOLE-PANEL smem, barrier-free mainloop.
// Tile 32i x 64j, 256 threads, thread tile 2i x 4j.
// Dynamic smem (216 KB): x panel [416][64] f32, y panel [416][32] u64
// (pre-dup'd), w [416] u64. ONE sync after the bulk load, then a flat
// 416-step loop: 3 LDS + 16 math per k, no barriers, no staging.
// Grid (8, 16) = 128 blocks.
// ======================================================================
#define XS_F   (HP * 64)                 // floats
#define YS_OFF (XS_F * 4)                // bytes
#define WS_OFF (YS_OFF + HP * 32 * 8)    // bytes
#define SMEM_BYTES (WS_OFF + HP * 8)     // 216,320 B

__global__ void __launch_bounds__(256)
pair_kernel(const float* __restrict__ b2p,
            float* __restrict__ out) {
    extern __shared__ __align__(16) char smem[];
    float* Xs  = reinterpret_cast<float*>(smem);            // [416][64]
    u64*   Ysd = reinterpret_cast<u64*>(smem + YS_OFF);     // [416][32]
    u64*   Ws  = reinterpret_cast<u64*>(smem + WS_OFF);     // [416]

    const int j0  = blockIdx.x * 64;
    const int i0  = blockIdx.y * 32;
    const int tid = threadIdx.x;    // 256
    const int tx  = tid & 15;       // j quad: 4 j each
    const int ty  = tid >> 4;       // i pair: 2 i each (0..15)

    // ---- bulk load phase (coalesced, high MLP) ----
    // x panel: 416 rows x 16 float4
    for (int idx = tid; idx < HP * 16; idx += 256) {
        int k = idx >> 4, q = idx & 15;
        *reinterpret_cast<float4*>(&Xs[k * 64 + q * 4]) =
            *reinterpret_cast<const float4*>(&g_hxT[k * NS + j0 + q * 4]);
    }
    // y panel: 416 rows x 16 ulonglong2
    for (int idx = tid; idx < HP * 16; idx += 256) {
        int k = idx >> 4, q = idx & 15;
        *reinterpret_cast<ulonglong2*>(&Ysd[k * 32 + q * 2]) =
            *reinterpret_cast<const ulonglong2*>(&g_hyTd[k * NS + i0 + q * 2]);
    }
    for (int idx = tid; idx < HP; idx += 256) Ws[idx] = g_w2h[idx];
    __syncthreads();   // the ONLY barrier before the epilogue

    // ---- flat mainloop: 416 iterations, no barriers ----
    u64 acc[2][2] = {};   // [ii][j-pair]
    const u64* xrow = reinterpret_cast<const u64*>(&Xs[tx * 4]);  // +k*32 (u64 units)
    const u64* yrow = &Ysd[ty * 2];                               // +k*32
    #pragma unroll 8
    for (int k = 0; k < HP; k++) {
        ulonglong2 xq = *reinterpret_cast<const ulonglong2*>(&xrow[k * 32]);
        ulonglong2 yd = *reinterpret_cast<const ulonglong2*>(&yrow[k * 32]);
        u64 wv = Ws[k];
        ABS_FMA2(acc[0][0], yd.x, xq.x, wv);
        ABS_FMA2(acc[0][1], yd.x, xq.y, wv);
        ABS_FMA2(acc[1][0], yd.y, xq.x, wv);
        ABS_FMA2(acc[1][1], yd.y, xq.y, wv);
    }

    // ---- fused epilogue ----
    const float b2 = b2p[0];
    const float4 rx = *reinterpret_cast<const float4*>(&g_rx[j0 + tx * 4]);
    const float rxq[4] = {rx.x, rx.y, rx.z, rx.w};
    float tSum = 0.f, dSum = 0.f;

    #pragma unroll
    for (int ii = 0; ii < 2; ii++) {
        const int i = i0 + ty * 2 + ii;
        const float ry = g_ry[i];
        float2 p01 = *reinterpret_cast<float2*>(&acc[ii][0]);
        float2 p23 = *reinterpret_cast<float2*>(&acc[ii][1]);
        float aq[4] = {p01.x, p01.y, p23.x, p23.y};
        float eRow = 0.f;
        #pragma unroll
        for (int q = 0; q < 4; q++) {
            float v = 0.5f * (ry + rxq[q]) + aq[q] + b2;
            float tt = fmaxf(v, 0.f) + log1pf(expf(-fabsf(v)));
            eRow += 1.f + expf(v);            // exp(softplus(v)) == 1 + e^v
            tSum += tt;
            if (j0 + tx * 4 + q == i) dSum += tt;
        }
        // row partial over 16 j-lanes (lanes 0-15 / 16-31 share ty)
        #pragma unroll
        for (int o = 8; o; o >>= 1)
            eRow += __shfl_down_sync(0xffffffffu, eRow, o, 16);
        if (tx == 0) atomicAdd(&g_expsum[i], eRow);
    }

    // block totals
    const int wid = tid >> 5, lane = tid & 31;
    #pragma unroll
    for (int o = 16; o; o >>= 1) {
        tSum += __shfl_down_sync(0xffffffffu, tSum, o);
        dSum += __shfl_down_sync(0xffffffffu, dSum, o);
    }
    __shared__ float wsum[8], wdia[8];
    if (lane == 0) { wsum[wid] = tSum; wdia[wid] = dSum; }
    __syncthreads();
    if (tid == 0) {
        float ts = 0.f, ds = 0.f;
        #pragma unroll
        for (int w = 0; w < 8; w++) { ts += wsum[w]; ds += wdia[w]; }
        atomicAdd(&g_tsum, (double)ts);
        atomicAdd(&g_dsum, (double)ds);
    }

    // ---- last block finalizes (double precision combine) ----
    __threadfence();
    __shared__ int ticket;
    if (tid == 0) ticket = atomicAdd(&g_cnt, 1);
    __syncthreads();
    if (ticket == 8 * 16 - 1) {
        g_rx[tid] = 0.f; g_rx[tid + 256] = 0.f;
        g_ry[tid] = 0.f; g_ry[tid + 256] = 0.f;
        double ls = log((double)g_expsum[tid]) + log((double)g_expsum[tid + 256]);
        #pragma unroll
        for (int o = 16; o; o >>= 1)
            ls += __shfl_down_sync(0xffffffffu, ls, o);
        __shared__ double lw[8];
        if (lane == 0) lw[wid] = ls;
        __syncthreads();
        if (tid == 0) {
            double lsum = 0.0;
            #pragma unroll
            for (int w = 0; w < 8; w++) lsum += lw[w];
            const double n = (double)NS;
            double t0_mean = g_dsum / n;
            out[0] = (float)(t0_mean - (lsum / n - log(n)));   // lower bound
            out[1] = (float)(t0_mean - g_tsum / (n * n));      // upper bound
            g_cnt = 0;
        }
    }
}

// ======================================================================
extern "C" void kernel_launch(void* const* d_in, const int* in_sizes, int n_in,
                              void* d_out, int out_size) {
    const float* x  = (const float*)d_in[0];
    const float* y  = (const float*)d_in[1];
    const float* W1 = (const float*)d_in[2];
    const float* b1 = (const float*)d_in[3];
    const float* W2 = (const float*)d_in[4];
    const float* b2 = (const float*)d_in[5];
    float* out = (float*)d_out;

    // allow 216 KB dynamic smem (idempotent; host-side attribute, not a
    // stream op — legal under graph capture)
    static bool attr_done = false;
    if (!attr_done) {
        cudaFuncSetAttribute(pair_kernel,
                             cudaFuncAttributeMaxDynamicSharedMemorySize,
                             SMEM_BYTES);
        attr_done = true;
    }

    dim3 ggrid(NS / 64, HP / 32, 2);          // (8, 13, 2) = 208 blocks
    gemm_h_kernel<<<ggrid, 128>>>(x, y, W1, b1, W2);

    dim3 pgrid(NS / 64, NS / 32);             // (8, 16) = 128 blocks
    pair_kernel<<<pgrid, 256, SMEM_BYTES>>>(b2, out);
}